// round 3
// baseline (speedup 1.0000x reference)
#include <cuda_runtime.h>

#define BB 256
#define TT 2048
#define II 64
#define HH 256

// Persistent scratch for the input projection (zero-init; t>=len never written).
__device__ float g_xp[(size_t)BB * TT * HH];

// ---------------------------------------------------------------------------
// f32x2 packed-math helpers
// ---------------------------------------------------------------------------
__device__ __forceinline__ unsigned long long pack2(float lo, float hi) {
    unsigned long long r;
    asm("mov.b64 %0, {%1,%2};" : "=l"(r) : "f"(lo), "f"(hi));
    return r;
}
__device__ __forceinline__ void ffma2(unsigned long long& acc,
                                      unsigned long long a, unsigned long long b) {
    asm("fma.rn.f32x2 %0, %1, %2, %0;" : "+l"(acc) : "l"(a), "l"(b));
}
__device__ __forceinline__ float2 unpack2(unsigned long long v) {
    float2 f;
    asm("mov.b64 {%0,%1}, %2;" : "=f"(f.x), "=f"(f.y) : "l"(v));
    return f;
}

// ---------------------------------------------------------------------------
// Kernel A: xp[b,t,h] = sum_i x[b,t,i]*W_ih[h,i] + b_ih[h] + b_hh[h], t < len[b]
// ---------------------------------------------------------------------------
__global__ __launch_bounds__(256) void xproj_kernel(
    const float* __restrict__ x,
    const int*   __restrict__ lengths,
    const float* __restrict__ W_ih,
    const float* __restrict__ b_ih,
    const float* __restrict__ b_hh)
{
    extern __shared__ float sm[];
    float* ws = sm;                 // [256][65]
    float* xs = sm + 256 * 65;      // [64][64]

    const int b  = blockIdx.y;
    const int t0 = blockIdx.x * 64;
    const int len = lengths[b];
    if (t0 >= len) return;
    const int tcnt = min(64, len - t0);
    const int tid = threadIdx.x;

    for (int idx = tid; idx < HH * II; idx += 256) {
        int h = idx >> 6, i = idx & 63;
        ws[h * 65 + i] = W_ih[idx];
    }
    const float* xbase = x + ((size_t)b * TT + t0) * II;
    for (int idx = tid; idx < tcnt * II; idx += 256) {
        xs[idx] = xbase[idx];
    }
    __syncthreads();

    const int h = tid;
    float w[II];
#pragma unroll
    for (int i = 0; i < II; i++) w[i] = ws[h * 65 + i];
    const float bias = b_ih[h] + b_hh[h];

    float* xpb = g_xp + ((size_t)b * TT + t0) * HH + h;
    const float4* xs4 = (const float4*)xs;

    for (int tt = 0; tt < tcnt; tt++) {
        float acc = bias;
#pragma unroll
        for (int i4 = 0; i4 < II / 4; i4++) {
            float4 xv = xs4[tt * (II / 4) + i4];
            acc = fmaf(xv.x, w[4 * i4 + 0], acc);
            acc = fmaf(xv.y, w[4 * i4 + 1], acc);
            acc = fmaf(xv.z, w[4 * i4 + 2], acc);
            acc = fmaf(xv.w, w[4 * i4 + 3], acc);
        }
        xpb[(size_t)tt * HH] = acc;
    }
}

// ---------------------------------------------------------------------------
// Kernel B: persistent scan, FFMA2 + store-time h duplication (zero MOVs).
// 128 CTAs x 256 threads, 2 batch rows/CTA.
// Thread (g=tid>>2, c=tid&3): owns j in [4g,4g+4), k-chunk k = 4i+c.
// h buffers: hA[k] = float4(h_b0,h_b0,h_b1,h_b1) -> one LDS.128 yields the two
// 64-bit duplicated operands for FFMA2 directly.
// W^T rows k<KSM in smem (stride RS=264 -> conflict-free LDS.128);
// rows k>=KSM packed in registers as f32x2 pairs.
// ---------------------------------------------------------------------------
#define RS 264
#define KSM 80
#define SMI (KSM / 4)            // 20 smem k-iterations
#define RGI ((HH - KSM) / 4)     // 44 register k-iterations

__global__ __launch_bounds__(256, 1) void scan_kernel(
    const float* __restrict__ W_hh,
    const int*   __restrict__ lengths,
    const float* __restrict__ W_fc,
    const float* __restrict__ b_fc,
    float*       __restrict__ out)
{
    extern __shared__ float sm[];
    float* WT_s = sm;                               // [KSM][RS]
    ulonglong2* hb0 = (ulonglong2*)(sm + KSM * RS); // [256] duplicated h, buf 0
    ulonglong2* hb1 = hb0 + HH;                     // [256] buf 1
    float* hlast = (float*)(hb1 + HH);              // [2][256]
    float* red   = hlast + 2 * HH;                  // [16]

    const int tid = threadIdx.x;
    const int c = tid & 3;
    const int g = tid >> 2;
    const int b0 = blockIdx.x * 2, b1 = b0 + 1;
    const int L0 = lengths[b0], L1 = lengths[b1];
    const int Tmax = max(L0, L1);

    // Stage W^T rows k < KSM into smem (coalesced read of W_hh).
    for (int idx = tid; idx < HH * HH; idx += 256) {
        int j = idx >> 8, k = idx & 255;
        float v = W_hh[idx];
        if (k < KSM) WT_s[k * RS + j] = v;
    }
    // Register-resident packed W pairs for k in [KSM, 256).
    unsigned long long wpA[RGI], wpB[RGI];
#pragma unroll
    for (int ii = 0; ii < RGI; ii++) {
        int k = KSM + 4 * ii + c;
        float w0 = __ldg(&W_hh[(4 * g + 0) * HH + k]);
        float w1 = __ldg(&W_hh[(4 * g + 1) * HH + k]);
        float w2 = __ldg(&W_hh[(4 * g + 2) * HH + k]);
        float w3 = __ldg(&W_hh[(4 * g + 3) * HH + k]);
        wpA[ii] = pack2(w0, w1);
        wpB[ii] = pack2(w2, w3);
    }
    ((float4*)hb0)[tid] = make_float4(0.f, 0.f, 0.f, 0.f);
    hlast[tid] = 0.f; hlast[HH + tid] = 0.f;
    __syncthreads();

    const float* xp0p = g_xp + (size_t)b0 * TT * HH + tid;   // j_own == tid
    const float* xp1p = g_xp + (size_t)b1 * TT * HH + tid;
    const unsigned base_s = c * RS + 4 * g;

    for (int t = 0; t < Tmax; t++) {
        const ulonglong2* hcur = (t & 1) ? hb1 : hb0;
        ulonglong2*       hnxt = (t & 1) ? hb0 : hb1;

        // prefetch xp for this step (consumed after the FMA block)
        float xpa = xp0p[(size_t)t * HH];
        float xpb = xp1p[(size_t)t * HH];

        unsigned long long aA = 0ull, aB = 0ull;   // batch b0: (j0,j1),(j2,j3)
        unsigned long long cA = 0ull, cB = 0ull;   // batch b1

#pragma unroll
        for (int i = 0; i < SMI; i++) {
            ulonglong2 wv = *(const ulonglong2*)&WT_s[base_s + (unsigned)(4 * i) * RS];
            ulonglong2 hv = hcur[4 * i + c];       // .x=(h0,h0) .y=(h1,h1)
            ffma2(aA, wv.x, hv.x); ffma2(aB, wv.y, hv.x);
            ffma2(cA, wv.x, hv.y); ffma2(cB, wv.y, hv.y);
        }
#pragma unroll
        for (int ii = 0; ii < RGI; ii++) {
            ulonglong2 hv = hcur[KSM + 4 * ii + c];
            ffma2(aA, wpA[ii], hv.x); ffma2(aB, wpB[ii], hv.x);
            ffma2(cA, wpA[ii], hv.y); ffma2(cB, wpB[ii], hv.y);
        }

        // Butterfly sum across the 4 k-split lanes (lane bits 0-1 == c).
#define REDUCE4(v) { v += __shfl_xor_sync(0xffffffffu, v, 1); \
                     v += __shfl_xor_sync(0xffffffffu, v, 2); }
        float2 fA = unpack2(aA), fB = unpack2(aB);
        float2 fC = unpack2(cA), fD = unpack2(cB);
        float a0 = fA.x, a1 = fA.y, a2 = fB.x, a3 = fB.y;
        float c0 = fC.x, c1 = fC.y, c2 = fD.x, c3 = fD.y;
        REDUCE4(a0) REDUCE4(a1) REDUCE4(a2) REDUCE4(a3)
        REDUCE4(c0) REDUCE4(c1) REDUCE4(c2) REDUCE4(c3)
#undef REDUCE4

        float s0 = (c == 0) ? a0 : (c == 1) ? a1 : (c == 2) ? a2 : a3;
        float s1 = (c == 0) ? c0 : (c == 1) ? c1 : (c == 2) ? c2 : c3;
        float h0n = tanhf(s0 + xpa);
        float h1n = tanhf(s1 + xpb);

        ((float4*)hnxt)[tid] = make_float4(h0n, h0n, h1n, h1n);
        if (t == L0 - 1) hlast[tid] = h0n;
        if (t == L1 - 1) hlast[HH + tid] = h1n;
        __syncthreads();   // hnxt visible; fences next-iter writes vs reads
    }

    // Final FC: out[b] = dot(hlast[b], W_fc) + b_fc
    float wf = W_fc[tid];
#pragma unroll
    for (int bb = 0; bb < 2; bb++) {
        float v = hlast[bb * HH + tid] * wf;
#pragma unroll
        for (int o = 16; o > 0; o >>= 1) v += __shfl_down_sync(0xffffffffu, v, o);
        if ((tid & 31) == 0) red[bb * 8 + (tid >> 5)] = v;
    }
    __syncthreads();
    if (tid < 2) {
        float s = b_fc[0];
#pragma unroll
        for (int w = 0; w < 8; w++) s += red[tid * 8 + w];
        out[b0 + tid] = s;
    }
}

// ---------------------------------------------------------------------------
extern "C" void kernel_launch(void* const* d_in, const int* in_sizes, int n_in,
                              void* d_out, int out_size)
{
    const float* x     = (const float*)d_in[0];
    const int*   lens  = (const int*)  d_in[1];
    const float* W_ih  = (const float*)d_in[2];
    const float* W_hh  = (const float*)d_in[3];
    const float* b_ih  = (const float*)d_in[4];
    const float* b_hh  = (const float*)d_in[5];
    const float* W_fc  = (const float*)d_in[6];
    const float* b_fc  = (const float*)d_in[7];
    float* out = (float*)d_out;

    const int A_SMEM = (256 * 65 + 64 * 64) * 4;                          // 82944 B
    const int B_SMEM = KSM * RS * 4 + 2 * HH * 16 + 2 * HH * 4 + 64;      // ~95 KB
    cudaFuncSetAttribute(xproj_kernel, cudaFuncAttributeMaxDynamicSharedMemorySize, A_SMEM);
    cudaFuncSetAttribute(scan_kernel,  cudaFuncAttributeMaxDynamicSharedMemorySize, B_SMEM);

    dim3 gA(TT / 64, BB);
    xproj_kernel<<<gA, 256, A_SMEM>>>(x, lens, W_ih, b_ih, b_hh);
    scan_kernel<<<BB / 2, 256, B_SMEM>>>(W_hh, lens, W_fc, b_fc, out);
}

// round 4
// speedup vs baseline: 1.3005x; 1.3005x over previous
#include <cuda_runtime.h>

#define BB 256
#define TT 2048
#define II 64
#define HH 256

// Persistent scratch for the input projection (zero-init; t>=len never written).
__device__ float g_xp[(size_t)BB * TT * HH];

typedef unsigned long long u64;

// ---------------------------------------------------------------------------
// f32x2 packed-math helpers
// ---------------------------------------------------------------------------
__device__ __forceinline__ u64 pack2(float lo, float hi) {
    u64 r; asm("mov.b64 %0, {%1,%2};" : "=l"(r) : "f"(lo), "f"(hi)); return r;
}
__device__ __forceinline__ u64 dup2(float v) {
    u64 r; asm("mov.b64 %0, {%1,%1};" : "=l"(r) : "f"(v)); return r;
}
__device__ __forceinline__ void ffma2(u64& acc, u64 a, u64 b) {
    asm("fma.rn.f32x2 %0, %1, %2, %0;" : "+l"(acc) : "l"(a), "l"(b));
}
__device__ __forceinline__ u64 add2(u64 a, u64 b) {
    u64 r; asm("add.rn.f32x2 %0, %1, %2;" : "=l"(r) : "l"(a), "l"(b)); return r;
}
__device__ __forceinline__ float2 unpack2(u64 v) {
    float2 f; asm("mov.b64 {%0,%1}, %2;" : "=f"(f.x), "=f"(f.y) : "l"(v)); return f;
}

// ---------------------------------------------------------------------------
// Kernel A: xp[b,t,h] = sum_i x[b,t,i]*W_ih[h,i] + b_ih[h] + b_hh[h], t < len[b]
// ---------------------------------------------------------------------------
__global__ __launch_bounds__(256) void xproj_kernel(
    const float* __restrict__ x,
    const int*   __restrict__ lengths,
    const float* __restrict__ W_ih,
    const float* __restrict__ b_ih,
    const float* __restrict__ b_hh)
{
    extern __shared__ float sm[];
    float* ws = sm;                 // [256][65]
    float* xs = sm + 256 * 65;      // [64][64]

    const int b  = blockIdx.y;
    const int t0 = blockIdx.x * 64;
    const int len = lengths[b];
    if (t0 >= len) return;
    const int tcnt = min(64, len - t0);
    const int tid = threadIdx.x;

    for (int idx = tid; idx < HH * II; idx += 256) {
        int h = idx >> 6, i = idx & 63;
        ws[h * 65 + i] = W_ih[idx];
    }
    const float* xbase = x + ((size_t)b * TT + t0) * II;
    for (int idx = tid; idx < tcnt * II; idx += 256) {
        xs[idx] = xbase[idx];
    }
    __syncthreads();

    const int h = tid;
    float w[II];
#pragma unroll
    for (int i = 0; i < II; i++) w[i] = ws[h * 65 + i];
    const float bias = b_ih[h] + b_hh[h];

    float* xpb = g_xp + ((size_t)b * TT + t0) * HH + h;
    const float4* xs4 = (const float4*)xs;

    for (int tt = 0; tt < tcnt; tt++) {
        float acc = bias;
#pragma unroll
        for (int i4 = 0; i4 < II / 4; i4++) {
            float4 xv = xs4[tt * (II / 4) + i4];
            acc = fmaf(xv.x, w[4 * i4 + 0], acc);
            acc = fmaf(xv.y, w[4 * i4 + 1], acc);
            acc = fmaf(xv.z, w[4 * i4 + 2], acc);
            acc = fmaf(xv.w, w[4 * i4 + 3], acc);
        }
        xpb[(size_t)tt * HH] = acc;
    }
}

// ---------------------------------------------------------------------------
// Kernel B: persistent scan. 128 CTAs x 256 threads, 2 batch rows/CTA.
// k-split 8 / j-octet: c=tid&7 handles k ≡ c (mod 8); g=tid>>3 owns j in
// [8g,8g+8). h stored interleaved float2 (h_b0[k], h_b1[k]) -> LDS.64 with
// only 4x lane duplication. W rows k<KSM in smem (RS=260 -> the 8 c-rows
// partition the 32 banks; conflict-free LDS.128); k>=KSM in 176 registers.
// Reduce-scatter over the 8 c-lanes; each lane finishes one (j-pair, batch).
// xp prefetched one step ahead.
// ---------------------------------------------------------------------------
#define RS 260
#define KSM 80
#define SMI (KSM / 8)            // 10 smem k-iterations
#define RGI ((HH - KSM) / 8)     // 22 register k-iterations

__global__ __launch_bounds__(256, 1) void scan_kernel(
    const float* __restrict__ W_hh,
    const int*   __restrict__ lengths,
    const float* __restrict__ W_fc,
    const float* __restrict__ b_fc,
    float*       __restrict__ out)
{
    extern __shared__ float sm[];
    float* WT_s = sm;                                // [KSM][RS]
    float2* hb0 = (float2*)(sm + KSM * RS);          // [256] (h_b0, h_b1)
    float2* hb1 = hb0 + HH;                          // [256]
    float* hlast = (float*)(hb1 + HH);               // [2][256]
    float* red   = hlast + 2 * HH;                   // [16]

    const int tid = threadIdx.x;
    const int c = tid & 7;
    const int g = tid >> 3;                          // 0..31
    const int b0 = blockIdx.x * 2, b1 = b0 + 1;
    const int L0 = lengths[b0], L1 = lengths[b1];
    const int Tmax = max(L0, L1);

    // Stage W^T rows k < KSM into smem (coalesced read of W_hh).
    for (int idx = tid; idx < HH * HH; idx += 256) {
        int j = idx >> 8, k = idx & 255;
        float v = W_hh[idx];
        if (k < KSM) WT_s[k * RS + j] = v;
    }
    // Register-resident packed W pairs for k in [KSM, 256), k = 8*(ii+SMI)+c.
    u64 wpA[RGI], wpB[RGI], wpC[RGI], wpD[RGI];
#pragma unroll
    for (int ii = 0; ii < RGI; ii++) {
        int k = 8 * (ii + SMI) + c;
        wpA[ii] = pack2(__ldg(&W_hh[(8*g+0)*HH + k]), __ldg(&W_hh[(8*g+1)*HH + k]));
        wpB[ii] = pack2(__ldg(&W_hh[(8*g+2)*HH + k]), __ldg(&W_hh[(8*g+3)*HH + k]));
        wpC[ii] = pack2(__ldg(&W_hh[(8*g+4)*HH + k]), __ldg(&W_hh[(8*g+5)*HH + k]));
        wpD[ii] = pack2(__ldg(&W_hh[(8*g+6)*HH + k]), __ldg(&W_hh[(8*g+7)*HH + k]));
    }
    hb0[tid] = make_float2(0.f, 0.f);
    hlast[tid] = 0.f; hlast[HH + tid] = 0.f;
    __syncthreads();

    // Per-lane final assignment after reduce-scatter:
    const int bf   = c >> 2;                 // 0 -> batch b0, 1 -> batch b1
    const int j0   = 8 * g + 2 * (c & 3);    // this lane's final j-pair
    const int Lsel = bf ? L1 : L0;
    const float* xpp = g_xp + (size_t)(bf ? b1 : b0) * TT * HH + j0;

    float2 xq = *(const float2*)xpp;         // xp for t = 0

    for (int t = 0; t < Tmax; t++) {
        const float2* hcur = (t & 1) ? hb1 : hb0;
        float2*       hnxt = (t & 1) ? hb0 : hb1;

        // prefetch xp for t+1 (consumed next iteration; fully hidden)
        int tn = min(t + 1, Tmax - 1);
        float2 xq_next = *(const float2*)(xpp + (size_t)tn * HH);

        u64 aA = 0, aB = 0, aC = 0, aD = 0;   // batch b0, j-pairs 0..3
        u64 cA = 0, cB = 0, cC = 0, cD = 0;   // batch b1

#pragma unroll
        for (int i = 0; i < SMI; i++) {
            int k = 8 * i + c;
            ulonglong2 w01 = *(const ulonglong2*)&WT_s[k * RS + 8 * g];
            ulonglong2 w23 = *(const ulonglong2*)&WT_s[k * RS + 8 * g + 4];
            float2 hv = hcur[k];
            u64 d0 = dup2(hv.x), d1 = dup2(hv.y);
            ffma2(aA, w01.x, d0); ffma2(aB, w01.y, d0);
            ffma2(aC, w23.x, d0); ffma2(aD, w23.y, d0);
            ffma2(cA, w01.x, d1); ffma2(cB, w01.y, d1);
            ffma2(cC, w23.x, d1); ffma2(cD, w23.y, d1);
        }
#pragma unroll
        for (int ii = 0; ii < RGI; ii++) {
            float2 hv = hcur[8 * (ii + SMI) + c];
            u64 d0 = dup2(hv.x), d1 = dup2(hv.y);
            ffma2(aA, wpA[ii], d0); ffma2(aB, wpB[ii], d0);
            ffma2(aC, wpC[ii], d0); ffma2(aD, wpD[ii], d0);
            ffma2(cA, wpA[ii], d1); ffma2(cB, wpB[ii], d1);
            ffma2(cC, wpC[ii], d1); ffma2(cD, wpD[ii], d1);
        }

        // Reduce-scatter across the 8 c-lanes (lane bits 0-2).
        u64 A[4] = {aA, aB, aC, aD};
        u64 C4[4] = {cA, cB, cC, cD};
        u64 R[4];
        const bool s1 = (c & 4) != 0;
#pragma unroll
        for (int p = 0; p < 4; p++) {
            u64 keep = s1 ? C4[p] : A[p];
            u64 send = s1 ? A[p] : C4[p];
            R[p] = add2(keep, __shfl_xor_sync(0xffffffffu, send, 4));
        }
        const bool s2 = (c & 2) != 0;
        u64 S[2];
#pragma unroll
        for (int q = 0; q < 2; q++) {
            u64 keep = s2 ? R[2 + q] : R[q];
            u64 send = s2 ? R[q] : R[2 + q];
            S[q] = add2(keep, __shfl_xor_sync(0xffffffffu, send, 2));
        }
        const bool s3 = (c & 1) != 0;
        u64 keep = s3 ? S[1] : S[0];
        u64 send = s3 ? S[0] : S[1];
        u64 F = add2(keep, __shfl_xor_sync(0xffffffffu, send, 1));

        float2 f = unpack2(F);
        float h0n = tanhf(f.x + xq.x);
        float h1n = tanhf(f.y + xq.y);

        float* hn = (float*)hnxt;
        hn[2 * j0 + bf] = h0n;
        hn[2 * (j0 + 1) + bf] = h1n;
        if (t == Lsel - 1) {
            hlast[bf * HH + j0] = h0n;
            hlast[bf * HH + j0 + 1] = h1n;
        }
        xq = xq_next;
        __syncthreads();   // hnxt visible; fences next-iter writes vs reads
    }

    // Final FC: out[b] = dot(hlast[b], W_fc) + b_fc
    float wf = W_fc[tid];
#pragma unroll
    for (int bb = 0; bb < 2; bb++) {
        float v = hlast[bb * HH + tid] * wf;
#pragma unroll
        for (int o = 16; o > 0; o >>= 1) v += __shfl_down_sync(0xffffffffu, v, o);
        if ((tid & 31) == 0) red[bb * 8 + (tid >> 5)] = v;
    }
    __syncthreads();
    if (tid < 2) {
        float s = b_fc[0];
#pragma unroll
        for (int w = 0; w < 8; w++) s += red[tid * 8 + w];
        out[b0 + tid] = s;
    }
}

// ---------------------------------------------------------------------------
extern "C" void kernel_launch(void* const* d_in, const int* in_sizes, int n_in,
                              void* d_out, int out_size)
{
    const float* x     = (const float*)d_in[0];
    const int*   lens  = (const int*)  d_in[1];
    const float* W_ih  = (const float*)d_in[2];
    const float* W_hh  = (const float*)d_in[3];
    const float* b_ih  = (const float*)d_in[4];
    const float* b_hh  = (const float*)d_in[5];
    const float* W_fc  = (const float*)d_in[6];
    const float* b_fc  = (const float*)d_in[7];
    float* out = (float*)d_out;

    const int A_SMEM = (256 * 65 + 64 * 64) * 4;                          // 82944 B
    const int B_SMEM = KSM * RS * 4 + 2 * HH * 8 + 2 * HH * 4 + 64;       // ~89.5 KB
    cudaFuncSetAttribute(xproj_kernel, cudaFuncAttributeMaxDynamicSharedMemorySize, A_SMEM);
    cudaFuncSetAttribute(scan_kernel,  cudaFuncAttributeMaxDynamicSharedMemorySize, B_SMEM);

    dim3 gA(TT / 64, BB);
    xproj_kernel<<<gA, 256, A_SMEM>>>(x, lens, W_ih, b_ih, b_hh);
    scan_kernel<<<BB / 2, 256, B_SMEM>>>(W_hh, lens, W_fc, b_fc, out);
}